// round 7
// baseline (speedup 1.0000x reference)
#include <cuda_runtime.h>
#include <cuda_bf16.h>
#include <cstdint>

// Problem constants: N=50000, E=600000, D=128, NF=3, V=8
#define D_DIM 128
#define NF_DIM 3
#define V_DIM 8
#define MAX_N 50048

// Scratch (device globals; no allocation allowed)
__device__ float g_acc[MAX_N * D_DIM];   // neighbor message sums (zeroed each call)
__device__ float g_deg[MAX_N];           // in-degree (zeroed each call)

// ---------------------------------------------------------------------------
// K1: edge scatter. One warp per edge; lane owns 4 contiguous dims.
// ---------------------------------------------------------------------------
__global__ void edge_scatter_kernel(const float* __restrict__ nfeat,
                                    const int* __restrict__ src,
                                    const int* __restrict__ dst,
                                    const int* __restrict__ eidx,
                                    const float* __restrict__ emb,
                                    int E) {
    int e = blockIdx.x * (blockDim.x >> 5) + (threadIdx.x >> 5);
    if (e >= E) return;
    int lane = threadIdx.x & 31;

    int s  = __ldg(src + e);
    int d  = __ldg(dst + e);
    int i0 = __ldg(eidx + e * NF_DIM + 0);
    int i1 = __ldg(eidx + e * NF_DIM + 1);
    int i2 = __ldg(eidx + e * NF_DIM + 2);

    int c = lane * 4;
    float4 v  = __ldg(reinterpret_cast<const float4*>(nfeat + (size_t)s * D_DIM + c));
    float4 e0 = __ldg(reinterpret_cast<const float4*>(emb + ((0 * V_DIM + i0) * D_DIM) + c));
    float4 e1 = __ldg(reinterpret_cast<const float4*>(emb + ((1 * V_DIM + i1) * D_DIM) + c));
    float4 e2 = __ldg(reinterpret_cast<const float4*>(emb + ((2 * V_DIM + i2) * D_DIM) + c));

    float mx = v.x + e0.x + e1.x + e2.x;
    float my = v.y + e0.y + e1.y + e2.y;
    float mz = v.z + e0.z + e1.z + e2.z;
    float mw = v.w + e0.w + e1.w + e2.w;

    float* p = g_acc + (size_t)d * D_DIM + c;
    asm volatile("red.global.add.v4.f32 [%0], {%1, %2, %3, %4};"
                 :: "l"(p), "f"(mx), "f"(my), "f"(mz), "f"(mw) : "memory");

    if (lane == 0) {
        atomicAdd(&g_deg[d], 1.0f);
    }
}

// ---------------------------------------------------------------------------
// K2: PERSISTENT bf16x3 GEMM with LDSM fragment loads.
//     grid=148 x 512 threads (16 warps). Warp tile 32x32 (2 m-tiles, 4 n-tiles).
//     out = ((nfeat + g_acc) / (g_deg + 1)) @ W + b
//     Smem bf16 arrays, row stride 136 bf16 (272B = 68 words):
//       Wth[n][k], Wtl[n][k] (W transposed), Hh[m][k], Hl[m][k]
//     ldmatrix conflict-free: stride 68 words == 4 banks shift/row,
//     8 rows x 16B sweep all 32 banks.
// ---------------------------------------------------------------------------
#define SBW 68                  // 32-bit words per smem row
#define ROWB (SBW * 4)          // row stride in bytes (272)

__device__ __forceinline__ uint32_t smem_u32(const void* p) {
    uint32_t a;
    asm("{ .reg .u64 t; cvta.to.shared.u64 t, %1; cvt.u32.u64 %0, t; }"
        : "=r"(a) : "l"(p));
    return a;
}

__device__ __forceinline__ void ldsm_x4(uint32_t* r, uint32_t addr) {
    asm volatile("ldmatrix.sync.aligned.m8n8.x4.shared.b16 {%0,%1,%2,%3}, [%4];"
                 : "=r"(r[0]), "=r"(r[1]), "=r"(r[2]), "=r"(r[3]) : "r"(addr));
}

__device__ __forceinline__ uint32_t pack_bf2(float a, float b) {
    __nv_bfloat162 h = __floats2bfloat162_rn(a, b);
    return *reinterpret_cast<uint32_t*>(&h);
}

__global__ void __launch_bounds__(512, 1)
gemm_bf16_kernel(const float* __restrict__ nfeat,
                 const float* __restrict__ W,
                 const float* __restrict__ b,
                 float* __restrict__ out, int N, int numTiles) {
    extern __shared__ uint32_t smu[];
    uint32_t* Wth = smu;                 // 128*68 words
    uint32_t* Wtl = Wth + D_DIM * SBW;
    uint32_t* Hh  = Wtl + D_DIM * SBW;
    uint32_t* Hl  = Hh + D_DIM * SBW;
    float* bs = reinterpret_cast<float*>(Hl + D_DIM * SBW);  // 128 floats

    int tid = threadIdx.x;

    // Stage W transposed, split into bf16 hi/lo (once per persistent block)
    {
        __nv_bfloat16* Wth_b = reinterpret_cast<__nv_bfloat16*>(Wth);
        __nv_bfloat16* Wtl_b = reinterpret_cast<__nv_bfloat16*>(Wtl);
        const float4* W4 = reinterpret_cast<const float4*>(W);
        for (int i = tid; i < (D_DIM * D_DIM) / 4; i += 512) {
            int k = i >> 5;
            int n4 = (i & 31) * 4;
            float4 w = __ldg(W4 + i);
            #pragma unroll
            for (int j = 0; j < 4; j++) {
                float x = (&w.x)[j];
                __nv_bfloat16 hb = __float2bfloat16_rn(x);
                __nv_bfloat16 lb = __float2bfloat16_rn(x - __bfloat162float(hb));
                Wth_b[(n4 + j) * (2 * SBW) + k] = hb;
                Wtl_b[(n4 + j) * (2 * SBW) + k] = lb;
            }
        }
        if (tid < D_DIM) bs[tid] = __ldg(b + tid);
    }

    int wid = tid >> 5;
    int lane = tid & 31;
    int gid = lane >> 2;        // 0..7
    int tig = lane & 3;         // 0..3
    int wr = (wid >> 2) * 32;   // warp row base 0/32/64/96
    int wc = (wid & 3) * 32;    // warp col base 0/32/64/96

    // Precompute per-lane LDSM base addresses (bytes, shared space).
    // Group g = lane>>3: g&1 selects row+8, g>>1 selects k+8.
    int lg  = lane >> 3;          // 0..3
    int lr8 = lane & 7;           // row within 8
    int arow = (lg & 1) * 8 + lr8;       // A: rows interleave 0..7 / 8..15
    int acol = (lg >> 1) * 8;            // A: k offset 0 / 8
    uint32_t sb = smem_u32(smu);
    uint32_t Ah_base = sb + ((D_DIM * SBW) * 2 * 4);        // Hh offset in bytes
    uint32_t Al_base = sb + ((D_DIM * SBW) * 3 * 4);
    uint32_t Bh_base = sb;                                  // Wth
    uint32_t Bl_base = sb + ((D_DIM * SBW) * 1 * 4);

    // A fragment addresses for mt=0,1 (rows wr+mt*16+arow, col acol)
    uint32_t ah_addr[2], al_addr[2];
    #pragma unroll
    for (int mt = 0; mt < 2; mt++) {
        uint32_t off = (uint32_t)(wr + mt * 16 + arow) * ROWB + acol * 2;
        ah_addr[mt] = Ah_base + off;
        al_addr[mt] = Al_base + off;
    }
    // B fragment addresses for np=0,1 (rows wc+np*16+arow, col acol)
    uint32_t bh_addr[2], bl_addr[2];
    #pragma unroll
    for (int np = 0; np < 2; np++) {
        uint32_t off = (uint32_t)(wc + np * 16 + arow) * ROWB + acol * 2;
        bh_addr[np] = Bh_base + off;
        bl_addr[np] = Bl_base + off;
    }

    const float4* nf4 = reinterpret_cast<const float4*>(nfeat);
    const float4* ac4 = reinterpret_cast<const float4*>(g_acc);

    for (int tile = blockIdx.x; tile < numTiles; tile += gridDim.x) {
        int row0 = tile * 128;

        __syncthreads();  // previous tile's MMA reads done before Hh/Hl overwrite

        // Stage H: h = (nfeat + acc) / (deg + 1), split bf16 hi/lo
        for (int i = tid; i < 128 * 32; i += 512) {
            int lr = i >> 5;
            int c4 = i & 31;
            int row = row0 + lr;
            float4 v = make_float4(0.f, 0.f, 0.f, 0.f);
            if (row < N) {
                float4 nv = __ldg(nf4 + (size_t)row * 32 + c4);
                float4 av = *(ac4 + (size_t)row * 32 + c4);
                float invd = 1.0f / (g_deg[row] + 1.0f);
                v = make_float4((nv.x + av.x) * invd, (nv.y + av.y) * invd,
                                (nv.z + av.z) * invd, (nv.w + av.w) * invd);
            }
            __nv_bfloat16 hx = __float2bfloat16_rn(v.x);
            __nv_bfloat16 hy = __float2bfloat16_rn(v.y);
            __nv_bfloat16 hz = __float2bfloat16_rn(v.z);
            __nv_bfloat16 hw = __float2bfloat16_rn(v.w);
            int base = lr * SBW + c4 * 2;
            Hh[base]     = pack_bf2(__bfloat162float(hx), __bfloat162float(hy));
            Hh[base + 1] = pack_bf2(__bfloat162float(hz), __bfloat162float(hw));
            Hl[base]     = pack_bf2(v.x - __bfloat162float(hx), v.y - __bfloat162float(hy));
            Hl[base + 1] = pack_bf2(v.z - __bfloat162float(hz), v.w - __bfloat162float(hw));
        }
        __syncthreads();

        float c[2][4][4];
        #pragma unroll
        for (int mt = 0; mt < 2; mt++)
            #pragma unroll
            for (int nt = 0; nt < 4; nt++)
                #pragma unroll
                for (int r = 0; r < 4; r++) c[mt][nt][r] = 0.f;

        #pragma unroll
        for (int kc = 0; kc < 8; kc++) {     // K chunk = 16
            uint32_t kb = kc * 32;           // byte advance per chunk (16 bf16)

            uint32_t ah[2][4], al[2][4];
            #pragma unroll
            for (int mt = 0; mt < 2; mt++) {
                ldsm_x4(ah[mt], ah_addr[mt] + kb);
                ldsm_x4(al[mt], al_addr[mt] + kb);
            }
            // bfr[np][g]: g0=b0 of tile 2np, g1=b0 of 2np+1, g2=b1 of 2np, g3=b1 of 2np+1
            uint32_t bhf[2][4], blf[2][4];
            #pragma unroll
            for (int np = 0; np < 2; np++) {
                ldsm_x4(bhf[np], bh_addr[np] + kb);
                ldsm_x4(blf[np], bl_addr[np] + kb);
            }

            #pragma unroll
            for (int mt = 0; mt < 2; mt++) {
                #pragma unroll
                for (int nt = 0; nt < 4; nt++) {
                    int np = nt >> 1, e = nt & 1;
                    uint32_t Bh[2] = { bhf[np][e], bhf[np][e + 2] };
                    uint32_t Bl[2] = { blf[np][e], blf[np][e + 2] };
                    #define MMA16(A, B)                                                  \
                        asm volatile(                                                    \
                            "mma.sync.aligned.m16n8k16.row.col.f32.bf16.bf16.f32 "       \
                            "{%0,%1,%2,%3}, {%4,%5,%6,%7}, {%8,%9}, {%0,%1,%2,%3};"      \
                            : "+f"(c[mt][nt][0]), "+f"(c[mt][nt][1]),                    \
                              "+f"(c[mt][nt][2]), "+f"(c[mt][nt][3])                     \
                            : "r"(A[0]), "r"(A[1]), "r"(A[2]), "r"(A[3]),                \
                              "r"(B[0]), "r"(B[1]))
                    MMA16(ah[mt], Bh);
                    MMA16(al[mt], Bh);
                    MMA16(ah[mt], Bl);
                    #undef MMA16
                }
            }
        }

        // Epilogue: add bias, store
        #pragma unroll
        for (int mt = 0; mt < 2; mt++) {
            #pragma unroll
            for (int nt = 0; nt < 4; nt++) {
                int col = wc + nt * 8 + 2 * tig;
                float bx = bs[col], by = bs[col + 1];
                int r_top = row0 + wr + mt * 16 + gid;
                if (r_top < N) {
                    float2 o = make_float2(c[mt][nt][0] + bx, c[mt][nt][1] + by);
                    *reinterpret_cast<float2*>(out + (size_t)r_top * D_DIM + col) = o;
                }
                int r_bot = r_top + 8;
                if (r_bot < N) {
                    float2 o = make_float2(c[mt][nt][2] + bx, c[mt][nt][3] + by);
                    *reinterpret_cast<float2*>(out + (size_t)r_bot * D_DIM + col) = o;
                }
            }
        }
    }
}

// ---------------------------------------------------------------------------
// Launch
// Inputs: nfeat[N*D] f32, src[E] i32, dst[E] i32, efeat_idx[E*3] i32,
//         edge_emb[3*8*128] f32, W[128*128] f32, b[128] f32 -> out float[N*128]
// ---------------------------------------------------------------------------
extern "C" void kernel_launch(void* const* d_in, const int* in_sizes, int n_in,
                              void* d_out, int out_size) {
    const float* nfeat = (const float*)d_in[0];
    const int*   src   = (const int*)d_in[1];
    const int*   dst   = (const int*)d_in[2];
    const int*   eidx  = (const int*)d_in[3];
    const float* emb   = (const float*)d_in[4];
    const float* W     = (const float*)d_in[5];
    const float* b     = (const float*)d_in[6];
    float* out = (float*)d_out;

    int N = in_sizes[0] / D_DIM;
    int E = in_sizes[1];

    // Zero accumulators (graph-capturable async memsets)
    void* acc_ptr = nullptr;
    void* deg_ptr = nullptr;
    cudaGetSymbolAddress(&acc_ptr, g_acc);
    cudaGetSymbolAddress(&deg_ptr, g_deg);
    cudaMemsetAsync(acc_ptr, 0, (size_t)N * D_DIM * sizeof(float));
    cudaMemsetAsync(deg_ptr, 0, (size_t)N * sizeof(float));

    // Edge scatter: 8 edges per 256-thread block
    edge_scatter_kernel<<<(E + 7) / 8, 256>>>(nfeat, src, dst, eidx, emb, E);

    // Persistent bf16x3 GEMM with LDSM
    int numTiles = (N + 127) / 128;
    int smem = (4 * D_DIM * SBW) * 4 + 128 * 4;  // 139264 + 512 bytes
    cudaFuncSetAttribute(gemm_bf16_kernel, cudaFuncAttributeMaxDynamicSharedMemorySize, smem);
    gemm_bf16_kernel<<<148, 512, smem>>>(nfeat, W, b, out, N, numTiles);
}